// round 3
// baseline (speedup 1.0000x reference)
#include <cuda_runtime.h>
#include <math.h>
#include <float.h>

// Accurate libdevice math (same routines XLA GPU lowers f32 exp/log to).
extern "C" __device__ float __nv_expf(float);
extern "C" __device__ float __nv_logf(float);

// B=64, T=500, NLOGIT=13, TR=5, NTDOAS=6, MAX_TAU=6
// pred  : (64,500,13,5,6) f32 -> 390 floats per (b,t)
// target: (64,500,5,5,13) f32 -> 325 floats per (b,t)
// mic_locs: (4,3) f32 ; out: [loss, acc] f32

__device__ double g_loss;
__device__ unsigned long long g_corr;
__device__ unsigned long long g_npred;

__global__ void tdoa_init() {
    g_loss = 0.0;
    g_corr = 0ull;
    g_npred = 0ull;
}

// Lexicographic (itertools) permutation decode, p in [0,120).
__device__ __forceinline__ void perm_decode(int p, int* out) {
    int avail[5] = {0, 1, 2, 3, 4};
    const int fact[4] = {24, 6, 2, 1};
#pragma unroll
    for (int i = 0; i < 4; i++) {
        int d = p / fact[i];
        p -= d * fact[i];
        out[i] = avail[d];
#pragma unroll
        for (int j = 0; j < 4; j++) {
            if (j >= d) avail[j] = avail[j + 1];
        }
    }
    out[4] = avail[0];
}

__global__ __launch_bounds__(192) void tdoa_main(
    const float* __restrict__ pred,
    const float* __restrict__ target,
    const float* __restrict__ mics)
{
    __shared__ float  s_pred[390];   // cl*30 + tr*6 + p
    __shared__ float  s_tgt[325];    // tr*65 + comp*13 + c
    __shared__ float  s_mics[12];
    __shared__ int    s_act[65];
    __shared__ int    s_sel[5];
    __shared__ int    s_v;
    __shared__ int    s_cls[5][6];   // [slot][pair]
    __shared__ float  s_lm[6][25];   // per warp: [k*5 + i]
    __shared__ int    s_pc[6][5];
    __shared__ double s_loss[6];
    __shared__ int    s_corr[6];

    const int bt   = blockIdx.x;
    const int tid  = threadIdx.x;
    const int warp = tid >> 5;
    const int lane = tid & 31;

    const float* pb = pred   + (size_t)bt * 390u;
    const float* tb = target + (size_t)bt * 325u;
    for (int i = tid; i < 390; i += 192) s_pred[i] = pb[i];
    for (int i = tid; i < 325; i += 192) s_tgt[i]  = tb[i];
    if (tid < 12) s_mics[tid] = mics[tid];
    if (tid < 30) s_cls[tid / 6][tid % 6] = 0;  // safe default
    __syncthreads();

    if (tid < 65) {
        int tr = tid / 13, c = tid - tr * 13;
        s_act[tid] = (s_tgt[tr * 65 + c] != 0.0f) ? 1 : 0;
    }
    __syncthreads();

    // stable selection of first <=5 active flat entries (f = tr*13 + c)
    if (tid == 0) {
        int v = 0;
#pragma unroll 1
        for (int f = 0; f < 65; f++) {
            if (s_act[f]) {
                if (v < 5) s_sel[v] = f;
                v++;
            }
        }
        s_v = (v < 5) ? v : 5;
    }
    __syncthreads();

    // TDOA class per (slot, pair); explicit IEEE ops (no FMA contraction).
    if (tid < 30) {
        int s  = tid / 6;
        int pr = tid - s * 6;
        if (s < s_v) {
            const int pa[6]  = {0, 0, 0, 1, 1, 2};
            const int pbx[6] = {1, 2, 3, 2, 3, 3};
            int f  = s_sel[s];
            int tr = f / 13, c = f - tr * 13;
            float dist = s_tgt[tr * 65 + 52 + c];
            float sx = __fmul_rn(s_tgt[tr * 65 + 13 + c], dist);
            float sy = __fmul_rn(s_tgt[tr * 65 + 26 + c], dist);
            float sz = __fmul_rn(s_tgt[tr * 65 + 39 + c], dist);
            int ma = pa[pr], mb = pbx[pr];
            float dxa = __fsub_rn(sx, s_mics[ma * 3 + 0]);
            float dya = __fsub_rn(sy, s_mics[ma * 3 + 1]);
            float dza = __fsub_rn(sz, s_mics[ma * 3 + 2]);
            float dxb = __fsub_rn(sx, s_mics[mb * 3 + 0]);
            float dyb = __fsub_rn(sy, s_mics[mb * 3 + 1]);
            float dzb = __fsub_rn(sz, s_mics[mb * 3 + 2]);
            float qa = __fadd_rn(__fadd_rn(__fmul_rn(dxa, dxa), __fmul_rn(dya, dya)), __fmul_rn(dza, dza));
            float qb = __fadd_rn(__fadd_rn(__fmul_rn(dxb, dxb), __fmul_rn(dyb, dyb)), __fmul_rn(dzb, dzb));
            float tdoa = __fsub_rn(__fsqrt_rn(qa), __fsqrt_rn(qb));
            s_cls[s][pr] = (int)rintf(__fdiv_rn(__fmul_rn(tdoa, 24000.0f), 343.0f)) + 6;
        }
    }
    __syncthreads();

    const int p   = warp;   // mic-pair handled by this warp
    const int myv = s_v;

    if (lane < 5) {
        const int i = lane;  // prediction track
        float shifted[13];
        float mx = -FLT_MAX;
        int   am = 0;
#pragma unroll
        for (int cl = 0; cl < 13; cl++) {
            float x = s_pred[cl * 30 + i * 6 + p];
            shifted[cl] = x;
            if (x > mx) { mx = x; am = cl; }  // first-occurrence argmax
        }
        float e[13];
#pragma unroll
        for (int cl = 0; cl < 13; cl++) {
            shifted[cl] = __fsub_rn(shifted[cl], mx);
            e[cl] = __nv_expf(shifted[cl]);
        }
        // Replicate XLA GPU column-reduction shuffle tree over 32 lanes
        // (leaves 13..31 are identity 0; +0 adds leave bits unchanged):
        //   off8 : b_k = e_k + e_{k+8}   (k<5),  b_k = e_k (k=5..7)
        //   off4 : c_k = b_k + b_{k+4}
        //   off2 : d_k = c_k + c_{k+2}
        //   off1 : sm  = d_0 + d_1
        float b0 = __fadd_rn(e[0], e[8]);
        float b1 = __fadd_rn(e[1], e[9]);
        float b2 = __fadd_rn(e[2], e[10]);
        float b3 = __fadd_rn(e[3], e[11]);
        float b4 = __fadd_rn(e[4], e[12]);
        float c0 = __fadd_rn(b0, b4);
        float c1 = __fadd_rn(b1, e[5]);
        float c2 = __fadd_rn(b2, e[6]);
        float c3 = __fadd_rn(b3, e[7]);
        float d0 = __fadd_rn(c0, c2);
        float d1 = __fadd_rn(c1, c3);
        float sm = __fadd_rn(d0, d1);
        float lse = __nv_logf(sm);
        s_pc[p][i] = am;
#pragma unroll
        for (int k = 0; k < 5; k++) {
            int idx = (k < myv) ? s_cls[k][p] : 0;
            float val = __fsub_rn(lse, shifted[idx]);
            s_lm[p][k * 5 + i] = (k < myv) ? val : 0.0f;
        }
    }
    __syncwarp();

    // 120-perm argmin; first-occurrence tie-break (lowest perm index).
    const float* lm = s_lm[p];
    float best = FLT_MAX;
    int   bidx = 1 << 20;
#pragma unroll
    for (int rep = 0; rep < 4; rep++) {
        int pe = lane + rep * 32;
        if (pe < 120) {
            int pm[5];
            perm_decode(pe, pm);
            float a0 = lm[      pm[0]];
            float a1 = lm[5  + pm[1]];
            float a2 = lm[10 + pm[2]];
            float a3 = lm[15 + pm[3]];
            float a4 = lm[20 + pm[4]];
            // Replicate XLA multi-row (8 threads/row) shuffle tree:
            //   ((a0+a4)+a2) + (a1+a3),  then divide by 5.
            float s0 = __fadd_rn(__fadd_rn(__fadd_rn(a0, a4), a2),
                                 __fadd_rn(a1, a3));
            float cst = __fdiv_rn(s0, 5.0f);
            if (cst < best) { best = cst; bidx = pe; }
        }
    }
#pragma unroll
    for (int off = 16; off; off >>= 1) {
        float ov = __shfl_down_sync(0xffffffffu, best, off);
        int   oi = __shfl_down_sync(0xffffffffu, bidx, off);
        if (ov < best || (ov == best && oi < bidx)) { best = ov; bidx = oi; }
    }

    if (lane == 0) {
        int pm[5];
        perm_decode(bidx, pm);
        int corr = 0;
#pragma unroll
        for (int i = 0; i < 5; i++) {
            int s = pm[i];  // tgt_perm[i] = tgt[perm[i]]
            if (s < myv && s_pc[p][i] == s_cls[s][p]) corr++;
        }
        s_loss[p] = (double)best;
        s_corr[p] = corr;
    }
    __syncthreads();

    if (tid == 0) {
        double L = 0.0;
        int    C = 0;
#pragma unroll
        for (int w = 0; w < 6; w++) { L += s_loss[w]; C += s_corr[w]; }
        atomicAdd(&g_loss, L);
        atomicAdd(&g_corr, (unsigned long long)C);
        atomicAdd(&g_npred, (unsigned long long)(6 * myv));
    }
}

__global__ void tdoa_fin(float* out, int n) {
    if (n >= 1) out[0] = (float)(g_loss / 192000.0);
    if (n >= 2) {
        unsigned long long np = g_npred;
        out[1] = (np > 0) ? (float)((double)g_corr / (double)np) : 0.0f;
    }
}

extern "C" void kernel_launch(void* const* d_in, const int* in_sizes, int n_in,
                              void* d_out, int out_size) {
    const float* pred   = (const float*)d_in[0];
    const float* target = (const float*)d_in[1];
    const float* mics   = (const float*)d_in[2];
    (void)in_sizes; (void)n_in;

    tdoa_init<<<1, 1>>>();
    tdoa_main<<<64 * 500, 192>>>(pred, target, mics);
    tdoa_fin<<<1, 1>>>((float*)d_out, out_size);
}

// round 4
// speedup vs baseline: 6.2897x; 6.2897x over previous
#include <cuda_runtime.h>
#include <math.h>
#include <float.h>

// Accurate libdevice math (same routines XLA GPU lowers f32 exp/log to).
extern "C" __device__ float __nv_expf(float);
extern "C" __device__ float __nv_logf(float);

// B=64, T=500 -> 32000 (b,t) rows; NLOGIT=13, TR=5, P=6 pairs.
// pred  : (64,500,13,5,6) f32 -> 390 floats per (b,t)
// target: (64,500,5,5,13) f32 -> 325 floats per (b,t)
// mic_locs: (4,3) f32 ; out: [loss, acc] f32

#define NBT  32000
#define WPB  8
#define NBLK (NBT / WPB)   // 4000

__device__ double g_ploss[NBLK];
__device__ int    g_pcorr[NBLK];
__device__ int    g_pnp[NBLK];

// Lexicographic (itertools) permutation -> packed 4-bit digits.
__device__ __forceinline__ unsigned perm_pack(int p) {
    int avail[5] = {0, 1, 2, 3, 4};
    const int fact[4] = {24, 6, 2, 1};
    unsigned pk = 0;
#pragma unroll
    for (int i = 0; i < 4; i++) {
        int d = p / fact[i];
        p -= d * fact[i];
        pk |= (unsigned)avail[d] << (4 * i);
#pragma unroll
        for (int j = 0; j < 4; j++)
            if (j >= d) avail[j] = avail[j + 1];
    }
    pk |= (unsigned)avail[0] << 16;
    return pk;
}

__global__ __launch_bounds__(256) void tdoa_main(
    const float* __restrict__ pred,
    const float* __restrict__ target,
    const float* __restrict__ mics)
{
    __shared__ float    s_pred[WPB][390];   // cl*30 + track*6 + pair
    __shared__ float    s_tgt[WPB][325];    // tr*65 + comp*13 + c
    __shared__ float    s_lm[WPB][150];     // pair*25 + slot*5 + track
    __shared__ int      s_cls[WPB][30];     // slot*6 + pair
    __shared__ int      s_pc[WPB][30];      // pair*5 + track
    __shared__ int      s_sel[WPB][5];
    __shared__ unsigned s_perm[120];
    __shared__ float    s_mics[12];
    __shared__ double   s_wloss[WPB];
    __shared__ int      s_wcorr[WPB];
    __shared__ int      s_wnp[WPB];

    const int tid  = threadIdx.x;
    const int w    = tid >> 5;
    const int lane = tid & 31;
    const int bt   = blockIdx.x * WPB + w;

    // ---- stage inputs (warp-coalesced) + block-shared tables ----
    const float* pb = pred   + (size_t)bt * 390u;
    const float* tb = target + (size_t)bt * 325u;
    for (int i = lane; i < 390; i += 32) s_pred[w][i] = pb[i];
    for (int i = lane; i < 325; i += 32) s_tgt[w][i]  = tb[i];
    if (tid < 120) s_perm[tid] = perm_pack(tid);
    if (tid < 12)  s_mics[tid] = mics[tid];
    __syncthreads();

    // ---- stable first-<=5 active selection via ballots (f = tr*13 + c) ----
    int f0 = lane;                 // 0..31
    int f1 = 32 + lane;            // 32..63
    int tr0 = f0 / 13, c0 = f0 - tr0 * 13;
    int tr1 = f1 / 13, c1 = f1 - tr1 * 13;
    unsigned b0 = __ballot_sync(0xffffffffu, s_tgt[w][tr0 * 65 + c0] != 0.0f);
    unsigned b1 = __ballot_sync(0xffffffffu, s_tgt[w][tr1 * 65 + c1] != 0.0f);
    int act64 = (s_tgt[w][4 * 65 + 12] != 0.0f) ? 1 : 0;   // f = 64
    unsigned long long bits = (unsigned long long)b0 |
                              ((unsigned long long)b1 << 32);
    int total = __popcll(bits) + act64;
    const int v = (total < 5) ? total : 5;

    if (lane < 5) {
        int fsel = 0;
        if (lane < v) {
            if (lane < __popcll(bits)) {
                unsigned long long t = bits;
#pragma unroll
                for (int j = 0; j < 4; j++)
                    if (j < lane) t &= t - 1;
                fsel = __ffsll((long long)t) - 1;
            } else {
                fsel = 64;
            }
        }
        s_sel[w][lane] = fsel;
    }
    __syncwarp();

    // ---- TDOA class per (slot, pair); explicit IEEE ops (no FMA) ----
    if (lane < 30) {
        int s  = lane / 6;
        int pr = lane - s * 6;
        int cls = 0;
        if (s < v) {
            const int pa[6]  = {0, 0, 0, 1, 1, 2};
            const int pbx[6] = {1, 2, 3, 2, 3, 3};
            int f  = s_sel[w][s];
            int tr = f / 13, c = f - tr * 13;
            float dist = s_tgt[w][tr * 65 + 52 + c];
            float sx = __fmul_rn(s_tgt[w][tr * 65 + 13 + c], dist);
            float sy = __fmul_rn(s_tgt[w][tr * 65 + 26 + c], dist);
            float sz = __fmul_rn(s_tgt[w][tr * 65 + 39 + c], dist);
            int ma = pa[pr], mb = pbx[pr];
            float dxa = __fsub_rn(sx, s_mics[ma * 3 + 0]);
            float dya = __fsub_rn(sy, s_mics[ma * 3 + 1]);
            float dza = __fsub_rn(sz, s_mics[ma * 3 + 2]);
            float dxb = __fsub_rn(sx, s_mics[mb * 3 + 0]);
            float dyb = __fsub_rn(sy, s_mics[mb * 3 + 1]);
            float dzb = __fsub_rn(sz, s_mics[mb * 3 + 2]);
            float qa = __fadd_rn(__fadd_rn(__fmul_rn(dxa, dxa), __fmul_rn(dya, dya)), __fmul_rn(dza, dza));
            float qb = __fadd_rn(__fadd_rn(__fmul_rn(dxb, dxb), __fmul_rn(dyb, dyb)), __fmul_rn(dzb, dzb));
            float tdoa = __fsub_rn(__fsqrt_rn(qa), __fsqrt_rn(qb));
            cls = (int)rintf(__fdiv_rn(__fmul_rn(tdoa, 24000.0f), 343.0f)) + 6;
        }
        s_cls[w][lane] = cls;
    }
    __syncwarp();

    // ---- log-softmax per (pair, track): 30 lanes in parallel ----
    if (lane < 30) {
        const int pair  = lane / 5;
        const int track = lane - pair * 5;
        float x[13];
        float mx = -FLT_MAX;
        int   am = 0;
#pragma unroll
        for (int cl = 0; cl < 13; cl++) {
            x[cl] = s_pred[w][cl * 30 + track * 6 + pair];
            if (x[cl] > mx) { mx = x[cl]; am = cl; }  // first-occurrence argmax
        }
        float e[13];
#pragma unroll
        for (int cl = 0; cl < 13; cl++)
            e[cl] = __nv_expf(__fsub_rn(x[cl], mx));
        // XLA GPU 32-lane column-reduction shuffle tree (leaves 13..31 == 0):
        float t0 = __fadd_rn(e[0], e[8]);
        float t1 = __fadd_rn(e[1], e[9]);
        float t2 = __fadd_rn(e[2], e[10]);
        float t3 = __fadd_rn(e[3], e[11]);
        float t4 = __fadd_rn(e[4], e[12]);
        float u0 = __fadd_rn(t0, t4);
        float u1 = __fadd_rn(t1, e[5]);
        float u2 = __fadd_rn(t2, e[6]);
        float u3 = __fadd_rn(t3, e[7]);
        float sm = __fadd_rn(__fadd_rn(u0, u2), __fadd_rn(u1, u3));
        float lse = __nv_logf(sm);
        s_pc[w][lane] = am;
#pragma unroll
        for (int k = 0; k < 5; k++) {
            int idx = (k < v) ? s_cls[w][k * 6 + pair] : 0;
            // lse - shifted[idx], with shifted[idx] = x[idx] - mx (same bits)
            float xv  = s_pred[w][idx * 30 + track * 6 + pair];
            float val = __fsub_rn(lse, __fsub_rn(xv, mx));
            s_lm[w][pair * 25 + k * 5 + track] = (k < v) ? val : 0.0f;
        }
    }
    __syncwarp();

    // ---- per-pair 120-perm argmin (first-occurrence tie-break) ----
    double wloss = 0.0;
    int    wcorr = 0;
#pragma unroll 1
    for (int pair = 0; pair < 6; pair++) {
        const float* lm = &s_lm[w][pair * 25];
        float best = FLT_MAX;
        int   bidx = 1 << 20;
#pragma unroll
        for (int rep = 0; rep < 4; rep++) {
            int pe = lane + rep * 32;
            if (pe < 120) {
                unsigned pk = s_perm[pe];
                float a0 = lm[       (pk       & 15)];
                float a1 = lm[ 5 +  ((pk >> 4) & 15)];
                float a2 = lm[10 +  ((pk >> 8) & 15)];
                float a3 = lm[15 +  ((pk >> 12) & 15)];
                float a4 = lm[20 +  ((pk >> 16) & 15)];
                // XLA multi-row shuffle tree: ((a0+a4)+a2)+(a1+a3), then /5
                float s0 = __fadd_rn(__fadd_rn(__fadd_rn(a0, a4), a2),
                                     __fadd_rn(a1, a3));
                float cst = __fdiv_rn(s0, 5.0f);
                if (cst < best) { best = cst; bidx = pe; }
            }
        }
#pragma unroll
        for (int off = 16; off; off >>= 1) {
            float ov = __shfl_down_sync(0xffffffffu, best, off);
            int   oi = __shfl_down_sync(0xffffffffu, bidx, off);
            if (ov < best || (ov == best && oi < bidx)) { best = ov; bidx = oi; }
        }
        if (lane == 0) {
            unsigned pk = s_perm[bidx];
#pragma unroll
            for (int i = 0; i < 5; i++) {
                int s = (pk >> (4 * i)) & 15;   // tgt_perm[i] = tgt[perm[i]]
                if (s < v && s_pc[w][pair * 5 + i] == s_cls[w][s * 6 + pair]) wcorr++;
            }
            wloss += (double)best;
        }
    }

    if (lane == 0) {
        s_wloss[w] = wloss;
        s_wcorr[w] = wcorr;
        s_wnp[w]   = 6 * v;
    }
    __syncthreads();

    if (tid == 0) {
        double L = 0.0;
        int    C = 0, NP = 0;
#pragma unroll
        for (int i = 0; i < WPB; i++) { L += s_wloss[i]; C += s_wcorr[i]; NP += s_wnp[i]; }
        g_ploss[blockIdx.x] = L;
        g_pcorr[blockIdx.x] = C;
        g_pnp[blockIdx.x]   = NP;
    }
}

__global__ __launch_bounds__(256) void tdoa_fin(float* out, int n) {
    __shared__ double sL[256];
    __shared__ long long sC[256], sN[256];
    const int tid = threadIdx.x;
    double L = 0.0;
    long long C = 0, NP = 0;
    for (int i = tid; i < NBLK; i += 256) {
        L  += g_ploss[i];
        C  += g_pcorr[i];
        NP += g_pnp[i];
    }
    sL[tid] = L; sC[tid] = C; sN[tid] = NP;
    __syncthreads();
    for (int off = 128; off; off >>= 1) {
        if (tid < off) {
            sL[tid] += sL[tid + off];
            sC[tid] += sC[tid + off];
            sN[tid] += sN[tid + off];
        }
        __syncthreads();
    }
    if (tid == 0) {
        if (n >= 1) out[0] = (float)(sL[0] / 192000.0);
        if (n >= 2) out[1] = (sN[0] > 0) ? (float)((double)sC[0] / (double)sN[0]) : 0.0f;
    }
}

extern "C" void kernel_launch(void* const* d_in, const int* in_sizes, int n_in,
                              void* d_out, int out_size) {
    const float* pred   = (const float*)d_in[0];
    const float* target = (const float*)d_in[1];
    const float* mics   = (const float*)d_in[2];
    (void)in_sizes; (void)n_in;

    tdoa_main<<<NBLK, 256>>>(pred, target, mics);
    tdoa_fin<<<1, 256>>>((float*)d_out, out_size);
}

// round 5
// speedup vs baseline: 7.4683x; 1.1874x over previous
#include <cuda_runtime.h>
#include <math.h>
#include <float.h>

// Accurate libdevice math (same routines XLA GPU lowers f32 exp/log to).
extern "C" __device__ float __nv_expf(float);
extern "C" __device__ float __nv_logf(float);

// B=64, T=500 -> 32000 (b,t) rows; NLOGIT=13, TR=5, P=6 pairs.
// pred  : (64,500,13,5,6) f32 -> 390 floats per (b,t)
// target: (64,500,5,5,13) f32 -> 325 floats per (b,t)
// mic_locs: (4,3) f32 ; out: [loss, acc] f32

#define NBT   32000
#define WPB   8
#define NBLK  (NBT / WPB)   // 4000
#define NBUCK 64

__device__ double    g_bl[NBUCK];   // zero-init at load; fin re-zeroes
__device__ long long g_bc[NBUCK];
__device__ long long g_bn[NBUCK];

// Lexicographic (itertools) permutation -> packed 4-bit digits.
__device__ __forceinline__ unsigned perm_pack(int p) {
    int avail[5] = {0, 1, 2, 3, 4};
    const int fact[4] = {24, 6, 2, 1};
    unsigned pk = 0;
#pragma unroll
    for (int i = 0; i < 4; i++) {
        int d = p / fact[i];
        p -= d * fact[i];
        pk |= (unsigned)avail[d] << (4 * i);
#pragma unroll
        for (int j = 0; j < 4; j++)
            if (j >= d) avail[j] = avail[j + 1];
    }
    pk |= (unsigned)avail[0] << 16;
    return pk;
}

__global__ __launch_bounds__(256, 6) void tdoa_main(
    const float* __restrict__ pred,
    const float* __restrict__ target,
    const float* __restrict__ mics)
{
    __shared__ __align__(16) float s_pred[WPB][390];  // cl*30 + track*6 + pair
    // s_tgt (325 f) and s_lm (150 f) have disjoint lifetimes -> overlay.
    __shared__ __align__(16) float s_u[WPB][325];
    __shared__ unsigned char s_cls[WPB][32];   // slot*6 + pair
    __shared__ unsigned char s_pc[WPB][32];    // pair*5 + track
    __shared__ unsigned char s_sel[WPB][8];
    __shared__ unsigned s_perm[128];           // padded; [120..127] = 0
    __shared__ float    s_mics[12];
    __shared__ double   s_wloss[WPB];
    __shared__ int      s_wcorr[WPB];
    __shared__ int      s_wnp[WPB];

    const int tid  = threadIdx.x;
    const int w    = tid >> 5;
    const int lane = tid & 31;
    const int bt   = blockIdx.x * WPB + w;

    float* s_tgt = s_u[w];   // phase 1
    float* s_lm  = s_u[w];   // phase 2 (pair*25 + slot*5 + track)

    // ---- stage inputs ----
    {
        const float2* pb2 = (const float2*)(pred + (size_t)bt * 390u); // 8B-aligned
        float2* sp2 = (float2*)&s_pred[w][0];
#pragma unroll
        for (int i = 0; i < 6; i++) sp2[lane + 32 * i] = pb2[lane + 32 * i];
        if (lane < 3) sp2[192 + lane] = pb2[192 + lane];
        const float* tb = target + (size_t)bt * 325u;
        for (int i = lane; i < 325; i += 32) s_tgt[i] = tb[i];
    }
    if (tid < 128) s_perm[tid] = (tid < 120) ? perm_pack(tid) : 0u;
    if (tid < 12)  s_mics[tid] = mics[tid];
    __syncthreads();

    // ---- stable first-<=5 active selection via ballots (f = tr*13 + c) ----
    int f0 = lane, f1 = 32 + lane;
    int tr0 = f0 / 13, c0 = f0 - tr0 * 13;
    int tr1 = f1 / 13, c1 = f1 - tr1 * 13;
    unsigned b0 = __ballot_sync(0xffffffffu, s_tgt[tr0 * 65 + c0] != 0.0f);
    unsigned b1 = __ballot_sync(0xffffffffu, s_tgt[tr1 * 65 + c1] != 0.0f);
    int act64 = (s_tgt[4 * 65 + 12] != 0.0f) ? 1 : 0;   // f = 64
    unsigned long long bits = (unsigned long long)b0 |
                              ((unsigned long long)b1 << 32);
    int total = __popcll(bits) + act64;
    const int v = (total < 5) ? total : 5;

    if (lane < 5) {
        int fsel = 0;
        if (lane < v) {
            if (lane < __popcll(bits)) {
                unsigned long long t = bits;
#pragma unroll
                for (int j = 0; j < 4; j++)
                    if (j < lane) t &= t - 1;
                fsel = __ffsll((long long)t) - 1;
            } else {
                fsel = 64;
            }
        }
        s_sel[w][lane] = (unsigned char)fsel;
    }
    __syncwarp();

    // ---- TDOA class per (slot, pair); explicit IEEE ops (no FMA) ----
    if (lane < 30) {
        int s  = lane / 6;
        int pr = lane - s * 6;
        int cls = 0;
        if (s < v) {
            const int pa[6]  = {0, 0, 0, 1, 1, 2};
            const int pbx[6] = {1, 2, 3, 2, 3, 3};
            int f  = s_sel[w][s];
            int tr = f / 13, c = f - tr * 13;
            float dist = s_tgt[tr * 65 + 52 + c];
            float sx = __fmul_rn(s_tgt[tr * 65 + 13 + c], dist);
            float sy = __fmul_rn(s_tgt[tr * 65 + 26 + c], dist);
            float sz = __fmul_rn(s_tgt[tr * 65 + 39 + c], dist);
            int ma = pa[pr], mb = pbx[pr];
            float dxa = __fsub_rn(sx, s_mics[ma * 3 + 0]);
            float dya = __fsub_rn(sy, s_mics[ma * 3 + 1]);
            float dza = __fsub_rn(sz, s_mics[ma * 3 + 2]);
            float dxb = __fsub_rn(sx, s_mics[mb * 3 + 0]);
            float dyb = __fsub_rn(sy, s_mics[mb * 3 + 1]);
            float dzb = __fsub_rn(sz, s_mics[mb * 3 + 2]);
            float qa = __fadd_rn(__fadd_rn(__fmul_rn(dxa, dxa), __fmul_rn(dya, dya)), __fmul_rn(dza, dza));
            float qb = __fadd_rn(__fadd_rn(__fmul_rn(dxb, dxb), __fmul_rn(dyb, dyb)), __fmul_rn(dzb, dzb));
            float tdoa = __fsub_rn(__fsqrt_rn(qa), __fsqrt_rn(qb));
            cls = (int)rintf(__fdiv_rn(__fmul_rn(tdoa, 24000.0f), 343.0f)) + 6;
        }
        s_cls[w][lane] = (unsigned char)cls;
    }
    __syncwarp();   // s_tgt dead after this point; s_lm may reuse the storage

    // ---- log-softmax per (pair, track): 30 lanes in parallel ----
    if (lane < 30) {
        const int pair  = lane / 5;
        const int track = lane - pair * 5;
        const int base  = track * 6 + pair;
        float x[13];
        float mx = -FLT_MAX;
        int   am = 0;
#pragma unroll
        for (int cl = 0; cl < 13; cl++) {
            x[cl] = s_pred[w][cl * 30 + base];
            if (x[cl] > mx) { mx = x[cl]; am = cl; }  // first-occurrence argmax
        }
        // XLA GPU 32-lane column-reduction tree (leaves 13..31 == 0); exps
        // consumed pairwise to limit live registers.
        float t0 = __fadd_rn(__nv_expf(__fsub_rn(x[0], mx)), __nv_expf(__fsub_rn(x[8],  mx)));
        float t1 = __fadd_rn(__nv_expf(__fsub_rn(x[1], mx)), __nv_expf(__fsub_rn(x[9],  mx)));
        float t2 = __fadd_rn(__nv_expf(__fsub_rn(x[2], mx)), __nv_expf(__fsub_rn(x[10], mx)));
        float t3 = __fadd_rn(__nv_expf(__fsub_rn(x[3], mx)), __nv_expf(__fsub_rn(x[11], mx)));
        float t4 = __fadd_rn(__nv_expf(__fsub_rn(x[4], mx)), __nv_expf(__fsub_rn(x[12], mx)));
        float u0 = __fadd_rn(t0, t4);
        float u1 = __fadd_rn(t1, __nv_expf(__fsub_rn(x[5], mx)));
        float u2 = __fadd_rn(t2, __nv_expf(__fsub_rn(x[6], mx)));
        float u3 = __fadd_rn(t3, __nv_expf(__fsub_rn(x[7], mx)));
        float sm = __fadd_rn(__fadd_rn(u0, u2), __fadd_rn(u1, u3));
        float lse = __nv_logf(sm);
        s_pc[w][pair * 5 + track] = (unsigned char)am;
        float vals[5];
#pragma unroll
        for (int k = 0; k < 5; k++) {
            int idx = (k < v) ? (int)s_cls[w][k * 6 + pair] : 0;
            // lse - shifted[idx], shifted[idx] = x[idx] - mx (same bits)
            float xv = s_pred[w][idx * 30 + base];
            vals[k] = (k < v) ? __fsub_rn(lse, __fsub_rn(xv, mx)) : 0.0f;
        }
        __syncwarp(0x3fffffffu);   // all s_tgt reads done before lm overwrite
#pragma unroll
        for (int k = 0; k < 5; k++)
            s_lm[pair * 25 + k * 5 + track] = vals[k];
    }
    __syncwarp();

    // ---- per-pair 120-perm argmin (first-occurrence tie-break) ----
    // Perm digits hoisted out of the pair loop.
    const unsigned pk0 = s_perm[lane];
    const unsigned pk1 = s_perm[lane + 32];
    const unsigned pk2 = s_perm[lane + 64];
    const unsigned pk3 = s_perm[lane + 96];

    double wloss = 0.0;
    int    wcorr = 0;
#pragma unroll 1
    for (int pair = 0; pair < 6; pair++) {
        const float* lm = &s_lm[pair * 25];
        // Lazy division: cost = div(s0,5) is monotone in s0, so only divide
        // when the raw sum strictly improves; on divided-tie keep the earlier
        // index (matches reference first-occurrence argmin bitwise).
        float bs0  = FLT_MAX;
        float bcst = FLT_MAX;
        int   bidx = 1 << 20;
#pragma unroll
        for (int rep = 0; rep < 4; rep++) {
            unsigned pk = (rep == 0) ? pk0 : (rep == 1) ? pk1 : (rep == 2) ? pk2 : pk3;
            int pe = lane + rep * 32;
            if (pe < 120) {
                float a0 = lm[       (pk        & 15)];
                float a1 = lm[ 5 +  ((pk >> 4)  & 15)];
                float a2 = lm[10 +  ((pk >> 8)  & 15)];
                float a3 = lm[15 +  ((pk >> 12) & 15)];
                float a4 = lm[20 +  ((pk >> 16) & 15)];
                // XLA tree: ((a0+a4)+a2)+(a1+a3), then /5
                float s0 = __fadd_rn(__fadd_rn(__fadd_rn(a0, a4), a2),
                                     __fadd_rn(a1, a3));
                if (s0 < bs0) {
                    float cst = __fdiv_rn(s0, 5.0f);
                    if (cst < bcst) { bcst = cst; bidx = pe; }
                    bs0 = s0;   // tighten raw bound either way
                }
            }
        }
#pragma unroll
        for (int off = 16; off; off >>= 1) {
            float ov = __shfl_down_sync(0xffffffffu, bcst, off);
            int   oi = __shfl_down_sync(0xffffffffu, bidx, off);
            if (ov < bcst || (ov == bcst && oi < bidx)) { bcst = ov; bidx = oi; }
        }
        if (lane == 0) {
            unsigned pk = s_perm[bidx];
#pragma unroll
            for (int i = 0; i < 5; i++) {
                int s = (pk >> (4 * i)) & 15;   // tgt_perm[i] = tgt[perm[i]]
                if (s < v && (int)s_pc[w][pair * 5 + i] == (int)s_cls[w][s * 6 + pair]) wcorr++;
            }
            wloss += (double)bcst;
        }
    }

    if (lane == 0) {
        s_wloss[w] = wloss;
        s_wcorr[w] = wcorr;
        s_wnp[w]   = 6 * v;
    }
    __syncthreads();

    if (tid == 0) {
        double L = 0.0;
        int    C = 0, NP = 0;
#pragma unroll
        for (int i = 0; i < WPB; i++) { L += s_wloss[i]; C += s_wcorr[i]; NP += s_wnp[i]; }
        int bk = blockIdx.x & (NBUCK - 1);
        atomicAdd(&g_bl[bk], L);
        atomicAdd((unsigned long long*)&g_bc[bk], (unsigned long long)C);
        atomicAdd((unsigned long long*)&g_bn[bk], (unsigned long long)NP);
    }
}

// Reads the 64 buckets, writes outputs, then re-zeroes the buckets so every
// kernel_launch invocation (correctness run and each graph replay) starts
// from a clean state. Single block => no race between read and zero.
__global__ void tdoa_fin(float* out, int n) {
    __shared__ double    sL[NBUCK];
    __shared__ long long sC[NBUCK], sN[NBUCK];
    const int t = threadIdx.x;   // 64 threads
    sL[t] = g_bl[t];
    sC[t] = g_bc[t];
    sN[t] = g_bn[t];
    __syncthreads();
    g_bl[t] = 0.0;
    g_bc[t] = 0;
    g_bn[t] = 0;
#pragma unroll
    for (int off = 32; off; off >>= 1) {
        if (t < off) {
            sL[t] += sL[t + off];
            sC[t] += sC[t + off];
            sN[t] += sN[t + off];
        }
        __syncthreads();
    }
    if (t == 0) {
        if (n >= 1) out[0] = (float)(sL[0] / 192000.0);
        if (n >= 2) out[1] = (sN[0] > 0) ? (float)((double)sC[0] / (double)sN[0]) : 0.0f;
    }
}

extern "C" void kernel_launch(void* const* d_in, const int* in_sizes, int n_in,
                              void* d_out, int out_size) {
    const float* pred   = (const float*)d_in[0];
    const float* target = (const float*)d_in[1];
    const float* mics   = (const float*)d_in[2];
    (void)in_sizes; (void)n_in;

    tdoa_main<<<NBLK, 256>>>(pred, target, mics);
    tdoa_fin<<<1, NBUCK>>>((float*)d_out, out_size);
}